// round 4
// baseline (speedup 1.0000x reference)
#include <cuda_runtime.h>
#include <math.h>

// ---------------- problem constants ----------------
#define KS    11
#define HI    384
#define HO    512
#define HOUT  (HO - KS + 1)     // 502
#define TW    32                // tile width (outputs)
#define TH    64                // tile height (outputs)
#define PW    (TW + KS - 1)     // 42
#define PH    (TH + KS - 1)     // 74
#define SW    44                // s12 row stride (ull) -> 352B, 16B multiple
#define HS    33                // hms/hx12 row stride (elements)
#define NTX   ((HOUT + TW - 1) / TW)   // 16
#define NTY   ((HOUT + TH - 1) / TH)   // 8
#define NTHREADS 512

typedef unsigned long long ull;

// Gaussian weights (sigma=1.5, ks=11), double-normalized, rounded to f32.
#define GW0  0.0010283801f
#define GW1  0.0075987582f
#define GW2  0.0360007722f
#define GW3  0.1093606884f
#define GW4  0.2130055383f
#define GW5  0.2660117256f

__device__ double        g_accum = 0.0;
__device__ unsigned int  g_count = 0;

// ---------------- f32x2 packed helpers ----------------
__device__ __forceinline__ ull splat2(float g) {
    ull r; asm("mov.b64 %0, {%1, %1};" : "=l"(r) : "f"(g)); return r;
}
__device__ __forceinline__ void up2(ull v, float& lo, float& hi) {
    asm("mov.b64 {%0, %1}, %2;" : "=f"(lo), "=f"(hi) : "l"(v));
}
__device__ __forceinline__ ull pk2(float lo, float hi) {
    ull r; asm("mov.b64 %0, {%1, %2};" : "=l"(r) : "f"(lo), "f"(hi)); return r;
}
__device__ __forceinline__ ull pfma(ull a, ull b, ull c) {
    ull d; asm("fma.rn.f32x2 %0, %1, %2, %3;" : "=l"(d) : "l"(a), "l"(b), "l"(c)); return d;
}
__device__ __forceinline__ ull pmul(ull a, ull b) {
    ull d; asm("mul.rn.f32x2 %0, %1, %2;" : "=l"(d) : "l"(a), "l"(b)); return d;
}

// dynamic smem layout (bytes)
#define OFF_S12   0                                 // ull  [PH][SW] = 26048
#define OFF_HMS   (OFF_S12 + PH * SW * 8)           // ull2 [PH][HS] = 39072
#define OFF_HX12  (OFF_HMS + PH * HS * 16)          // f32  [PH][HS] =  9768
#define OFF_RED   (OFF_HX12 + PH * HS * 4)
#define SMEM_BYTES (OFF_RED + 128)                  // ~75 KB -> 2 CTAs/SM

// coefficient index with symmetry (constant-folds under full unroll)
#define GWC(k) ((k) < 6 ? (k) : 10 - (k))

// ---------------- single fused kernel ----------------
__global__ void __launch_bounds__(NTHREADS, 2)
ssim_tile_kernel(const float* __restrict__ input,   // [96, 384, 384]
                 const float* __restrict__ target,  // [96, 512, 512]
                 float* __restrict__ out,
                 long long count, unsigned int nblocks)
{
    extern __shared__ char smem[];
    ull        (*s12)[SW]  = (ull (*)[SW])(smem + OFF_S12);
    ulonglong2 (*hms)[HS]  = (ulonglong2 (*)[HS])(smem + OFF_HMS);
    float      (*hx12)[HS] = (float (*)[HS])(smem + OFF_HX12);
    float      *redbuf     = (float*)(smem + OFF_RED);

    const int img = blockIdx.z;
    const int ty0 = blockIdx.y * TH;
    const int tx0 = blockIdx.x * TW;
    const int tid = threadIdx.x;

    const float GW[6] = {GW0, GW1, GW2, GW3, GW4, GW5};
    ull CS[6];
    #pragma unroll
    for (int k = 0; k < 6; k++) CS[k] = splat2(GW[k]);

    const float* inp = input  + (size_t)img * (HI * HI);
    const float* tgt = target + (size_t)img * (HO * HO);

    // ---- load: target direct, img1 bilinear (exact integer index math) ----
    for (int e = tid; e < PH * PW; e += NTHREADS) {
        int r = e / PW;
        int c = e - r * PW;
        int gy = min(ty0 + r, HO - 1);
        int gx = min(tx0 + c, HO - 1);

        float t2 = tgt[gy * HO + gx];

        int py  = gy * (HI - 1);
        int iy0 = py / (HO - 1);
        float wy = (float)(py - iy0 * (HO - 1)) * (1.0f / (float)(HO - 1));
        int iy1 = min(iy0 + 1, HI - 1);
        int px  = gx * (HI - 1);
        int ix0 = px / (HO - 1);
        float wx = (float)(px - ix0 * (HO - 1)) * (1.0f / (float)(HO - 1));
        int ix1 = min(ix0 + 1, HI - 1);

        float a  = inp[iy0 * HI + ix0];
        float b  = inp[iy0 * HI + ix1];
        float cc = inp[iy1 * HI + ix0];
        float d  = inp[iy1 * HI + ix1];
        float top = a  * (1.0f - wx) + b * wx;
        float bot = cc * (1.0f - wx) + d * wx;
        float v1  = top * (1.0f - wy) + bot * wy;

        s12[r][c] = pk2(v1, t2);
    }
    __syncthreads();

    // ---- horizontal pass: 4 output cols per task, 14-tap window,
    //      s12 read as aligned 16B pairs ----
    for (int e = tid; e < PH * 8; e += NTHREADS) {
        int r  = e >> 3;
        int c0 = (e & 7) << 2;

        ull aM[4] = {0, 0, 0, 0};
        ull aS[4] = {0, 0, 0, 0};
        float aX[4] = {0.f, 0.f, 0.f, 0.f};

        #pragma unroll
        for (int jj = 0; jj < 7; jj++) {
            ulonglong2 pr = *reinterpret_cast<const ulonglong2*>(&s12[r][c0 + 2 * jj]);
            #pragma unroll
            for (int h = 0; h < 2; h++) {
                int j = 2 * jj + h;
                ull pk = h ? pr.y : pr.x;
                float p1, p2;
                up2(pk, p1, p2);
                ull sq = pmul(pk, pk);
                float p12 = p1 * p2;
                #pragma unroll
                for (int o = 0; o < 4; o++) {
                    int k = j - o;
                    if (k >= 0 && k < KS) {
                        aM[o] = pfma(pk, CS[GWC(k)], aM[o]);
                        aS[o] = pfma(sq, CS[GWC(k)], aS[o]);
                        aX[o] = fmaf(GW[GWC(k)], p12, aX[o]);
                    }
                }
            }
        }
        #pragma unroll
        for (int o = 0; o < 4; o++) {
            hms[r][c0 + o]  = make_ulonglong2(aM[o], aS[o]);
            hx12[r][c0 + o] = aX[o];
        }
    }
    __syncthreads();

    // ---- vertical pass: 16 warps, 4 output rows per thread, 14-tap window ----
    const int lx = tid & 31;
    const int o0 = (tid >> 5) << 2;     // warp w -> rows 4w..4w+3

    ull aM[4], aS[4];
    float aX[4];
    #pragma unroll
    for (int o = 0; o < 4; o++) { aM[o] = 0; aS[o] = 0; aX[o] = 0.f; }

    #pragma unroll
    for (int rel = 0; rel < 14; rel++) {
        int rr = o0 + rel;
        ulonglong2 vms = hms[rr][lx];
        float vX = hx12[rr][lx];
        #pragma unroll
        for (int o = 0; o < 4; o++) {
            int k = rel - o;
            if (k >= 0 && k < KS) {
                aM[o] = pfma(vms.x, CS[GWC(k)], aM[o]);
                aS[o] = pfma(vms.y, CS[GWC(k)], aS[o]);
                aX[o] = fmaf(GW[GWC(k)], vX, aX[o]);
            }
        }
    }

    // ---- SSIM map + local sum ----
    const float C1 = 1e-4f;
    const float C2 = 9e-4f;
    float lsum = 0.f;
    const int gx = tx0 + lx;

    #pragma unroll
    for (int o = 0; o < 4; o++) {
        int gy = ty0 + o0 + o;
        if (gy < HOUT && gx < HOUT) {
            float mu1, mu2, x11, x22;
            up2(aM[o], mu1, mu2);
            up2(aS[o], x11, x22);
            float mu1sq = mu1 * mu1;
            float mu2sq = mu2 * mu2;
            float mu12  = mu1 * mu2;
            float sig1  = x11 - mu1sq;
            float sig2  = x22 - mu2sq;
            float sig12 = aX[o] - mu12;
            float v1 = 2.0f * sig12 + C2;
            float v2 = sig1 + sig2 + C2;
            float num = (2.0f * mu12 + C1) * v1;
            float den = (mu1sq + mu2sq + C1) * v2;
            lsum += __fdividef(num, den);
        }
    }

    // ---- block reduction (16 warps) ----
    #pragma unroll
    for (int off = 16; off > 0; off >>= 1)
        lsum += __shfl_down_sync(0xFFFFFFFFu, lsum, off);
    int lane = tid & 31;
    int wid  = tid >> 5;
    if (lane == 0) redbuf[wid] = lsum;
    __syncthreads();
    if (tid == 0) {
        float v = 0.f;
        #pragma unroll
        for (int w = 0; w < 16; w++) v += redbuf[w];
        atomicAdd(&g_accum, (double)v);
        __threadfence();
        unsigned int old = atomicAdd(&g_count, 1u);
        if (old == nblocks - 1u) {
            double mean = g_accum / (double)count;
            double loss = 1.0 - mean;
            if (loss < 0.0) loss = 0.0;
            if (loss > 1.0) loss = 1.0;
            out[0] = (float)loss;
            g_accum = 0.0;
            g_count = 0u;
        }
    }
}

extern "C" void kernel_launch(void* const* d_in, const int* in_sizes, int n_in,
                              void* d_out, int out_size) {
    const float* input  = (const float*)d_in[0];
    const float* target = (const float*)d_in[1];
    int sz0 = in_sizes[0], sz1 = in_sizes[1];
    if (sz0 > sz1) {
        const float* t = input; input = target; target = t;
        int ts = sz0; sz0 = sz1; sz1 = ts;
    }
    int n_img = sz0 / (HI * HI);   // 96

    static bool attr_set = false;
    if (!attr_set) {
        cudaFuncSetAttribute(ssim_tile_kernel,
                             cudaFuncAttributeMaxDynamicSharedMemorySize, SMEM_BYTES);
        attr_set = true;
    }

    dim3 grid(NTX, NTY, n_img);
    unsigned int nblocks = NTX * NTY * (unsigned int)n_img;
    long long count = (long long)n_img * HOUT * HOUT;

    ssim_tile_kernel<<<grid, NTHREADS, SMEM_BYTES>>>(input, target, (float*)d_out,
                                                     count, nblocks);
}

// round 5
// speedup vs baseline: 1.0495x; 1.0495x over previous
#include <cuda_runtime.h>
#include <math.h>

// ---------------- problem constants ----------------
#define KS    11
#define HI    384
#define HO    512
#define HOUT  (HO - KS + 1)     // 502
#define TILE  32
#define PATCH (TILE + KS - 1)   // 42
#define SW    44                // s12 row stride (ull)
#define HS    33                // hbuf row stride
#define NT    ((HOUT + TILE - 1) / TILE)  // 16

typedef unsigned long long ull;

// Gaussian weights (sigma=1.5, ks=11), double-normalized, rounded to f32.
#define GW0  0.0010283801f
#define GW1  0.0075987582f
#define GW2  0.0360007722f
#define GW3  0.1093606884f
#define GW4  0.2130055383f
#define GW5  0.2660117256f

__device__ double        g_accum = 0.0;
__device__ unsigned int  g_count = 0;

// ---------------- f32x2 packed helpers ----------------
__device__ __forceinline__ ull splat2(float g) {
    ull r; asm("mov.b64 %0, {%1, %1};" : "=l"(r) : "f"(g)); return r;
}
__device__ __forceinline__ void up2(ull v, float& lo, float& hi) {
    asm("mov.b64 {%0, %1}, %2;" : "=f"(lo), "=f"(hi) : "l"(v));
}
__device__ __forceinline__ ull pk2(float lo, float hi) {
    ull r; asm("mov.b64 %0, {%1, %2};" : "=l"(r) : "f"(lo), "f"(hi)); return r;
}
__device__ __forceinline__ ull pfma(ull a, ull b, ull c) {
    ull d; asm("fma.rn.f32x2 %0, %1, %2, %3;" : "=l"(d) : "l"(a), "l"(b), "l"(c)); return d;
}
__device__ __forceinline__ ull pmul(ull a, ull b) {
    ull d; asm("mul.rn.f32x2 %0, %1, %2;" : "=l"(d) : "l"(a), "l"(b)); return d;
}

// coefficient index with symmetry (constant-folds under full unroll)
#define GWC(k) ((k) < 6 ? (k) : 10 - (k))

// ---------------- single fused kernel ----------------
__global__ void __launch_bounds__(256, 4)
ssim_tile_kernel(const float* __restrict__ input,   // [96, 384, 384]
                 const float* __restrict__ target,  // [96, 512, 512]
                 float* __restrict__ out,
                 long long count, unsigned int nblocks)
{
    __shared__ ull   s12[PATCH][SW];      // (img1, img2) interleaved   14784 B
    __shared__ ull   hmu[PATCH][HS];      // (mu1h, mu2h)               11088 B
    __shared__ ull   hsq[PATCH][HS];      // (x11h, x22h)               11088 B
    __shared__ float hx12[PATCH][HS];     // x12h                        5544 B
    __shared__ float redbuf[8];

    const int img = blockIdx.z;
    const int ty0 = blockIdx.y * TILE;
    const int tx0 = blockIdx.x * TILE;
    const int tid = threadIdx.x;

    const float GW[6] = {GW0, GW1, GW2, GW3, GW4, GW5};
    ull CS[6];
    #pragma unroll
    for (int k = 0; k < 6; k++) CS[k] = splat2(GW[k]);

    const float* inp = input  + (size_t)img * (HI * HI);
    const float* tgt = target + (size_t)img * (HO * HO);

    // ---- load: target direct, img1 bilinear (exact integer index math) ----
    for (int e = tid; e < PATCH * PATCH; e += 256) {
        int r = e / PATCH;
        int c = e - r * PATCH;
        int gy = min(ty0 + r, HO - 1);
        int gx = min(tx0 + c, HO - 1);

        float t2 = tgt[gy * HO + gx];

        int py  = gy * (HI - 1);
        int iy0 = py / (HO - 1);
        float wy = (float)(py - iy0 * (HO - 1)) * (1.0f / (float)(HO - 1));
        int iy1 = min(iy0 + 1, HI - 1);
        int px  = gx * (HI - 1);
        int ix0 = px / (HO - 1);
        float wx = (float)(px - ix0 * (HO - 1)) * (1.0f / (float)(HO - 1));
        int ix1 = min(ix0 + 1, HI - 1);

        float a  = inp[iy0 * HI + ix0];
        float b  = inp[iy0 * HI + ix1];
        float cc = inp[iy1 * HI + ix0];
        float d  = inp[iy1 * HI + ix1];
        float top = a  * (1.0f - wx) + b * wx;
        float bot = cc * (1.0f - wx) + d * wx;
        float v1  = top * (1.0f - wy) + bot * wy;

        s12[r][c] = pk2(v1, t2);
    }
    __syncthreads();

    // ---- horizontal pass: 4 output cols per task, sliding 14-tap window ----
    for (int e = tid; e < PATCH * 8; e += 256) {
        int r  = e >> 3;
        int c0 = (e & 7) << 2;

        ull aM[4] = {0, 0, 0, 0};
        ull aS[4] = {0, 0, 0, 0};
        float aX[4] = {0.f, 0.f, 0.f, 0.f};

        #pragma unroll
        for (int j = 0; j < 14; j++) {
            ull pk = s12[r][c0 + j];
            float p1, p2;
            up2(pk, p1, p2);
            ull sq = pmul(pk, pk);
            float p12 = p1 * p2;
            #pragma unroll
            for (int o = 0; o < 4; o++) {
                int k = j - o;
                if (k >= 0 && k < KS) {
                    aM[o] = pfma(pk, CS[GWC(k)], aM[o]);
                    aS[o] = pfma(sq, CS[GWC(k)], aS[o]);
                    aX[o] = fmaf(GW[GWC(k)], p12, aX[o]);
                }
            }
        }
        #pragma unroll
        for (int o = 0; o < 4; o++) {
            hmu[r][c0 + o]  = aM[o];
            hsq[r][c0 + o]  = aS[o];
            hx12[r][c0 + o] = aX[o];
        }
    }
    __syncthreads();

    // ---- vertical pass: 8 warps x 4 rows/thread, sliding 14-tap window ----
    const int lx = tid & 31;
    const int o0 = (tid >> 5) << 2;     // warp w -> rows 4w..4w+3

    ull aM[4], aS[4];
    float aX[4];
    #pragma unroll
    for (int o = 0; o < 4; o++) { aM[o] = 0; aS[o] = 0; aX[o] = 0.f; }

    #pragma unroll
    for (int rel = 0; rel < 14; rel++) {
        int rr = o0 + rel;
        ull vM   = hmu[rr][lx];
        ull vS   = hsq[rr][lx];
        float vX = hx12[rr][lx];
        #pragma unroll
        for (int o = 0; o < 4; o++) {
            int k = rel - o;
            if (k >= 0 && k < KS) {
                aM[o] = pfma(vM, CS[GWC(k)], aM[o]);
                aS[o] = pfma(vS, CS[GWC(k)], aS[o]);
                aX[o] = fmaf(GW[GWC(k)], vX, aX[o]);
            }
        }
    }

    // ---- SSIM map + local sum ----
    const float C1 = 1e-4f;
    const float C2 = 9e-4f;
    float lsum = 0.f;
    const int gx = tx0 + lx;

    #pragma unroll
    for (int o = 0; o < 4; o++) {
        int gy = ty0 + o0 + o;
        if (gy < HOUT && gx < HOUT) {
            float mu1, mu2, x11, x22;
            up2(aM[o], mu1, mu2);
            up2(aS[o], x11, x22);
            float mu1sq = mu1 * mu1;
            float mu2sq = mu2 * mu2;
            float mu12  = mu1 * mu2;
            float sig1  = x11 - mu1sq;
            float sig2  = x22 - mu2sq;
            float sig12 = aX[o] - mu12;
            float v1 = 2.0f * sig12 + C2;
            float v2 = sig1 + sig2 + C2;
            float num = (2.0f * mu12 + C1) * v1;
            float den = (mu1sq + mu2sq + C1) * v2;
            lsum += __fdividef(num, den);
        }
    }

    // ---- block reduction (8 warps) ----
    #pragma unroll
    for (int off = 16; off > 0; off >>= 1)
        lsum += __shfl_down_sync(0xFFFFFFFFu, lsum, off);
    int lane = tid & 31;
    int wid  = tid >> 5;
    if (lane == 0) redbuf[wid] = lsum;
    __syncthreads();
    if (tid == 0) {
        float v = 0.f;
        #pragma unroll
        for (int w = 0; w < 8; w++) v += redbuf[w];
        atomicAdd(&g_accum, (double)v);
        __threadfence();
        unsigned int old = atomicAdd(&g_count, 1u);
        if (old == nblocks - 1u) {
            double mean = g_accum / (double)count;
            double loss = 1.0 - mean;
            if (loss < 0.0) loss = 0.0;
            if (loss > 1.0) loss = 1.0;
            out[0] = (float)loss;
            g_accum = 0.0;
            g_count = 0u;
        }
    }
}

extern "C" void kernel_launch(void* const* d_in, const int* in_sizes, int n_in,
                              void* d_out, int out_size) {
    const float* input  = (const float*)d_in[0];
    const float* target = (const float*)d_in[1];
    int sz0 = in_sizes[0], sz1 = in_sizes[1];
    if (sz0 > sz1) {
        const float* t = input; input = target; target = t;
        int ts = sz0; sz0 = sz1; sz1 = ts;
    }
    int n_img = sz0 / (HI * HI);   // 96

    dim3 grid(NT, NT, n_img);
    unsigned int nblocks = NT * NT * (unsigned int)n_img;
    long long count = (long long)n_img * HOUT * HOUT;

    ssim_tile_kernel<<<grid, 256>>>(input, target, (float*)d_out, count, nblocks);
}

// round 6
// speedup vs baseline: 1.0632x; 1.0130x over previous
#include <cuda_runtime.h>
#include <math.h>

// ---------------- problem constants ----------------
#define KS    11
#define HI    384
#define HO    512
#define HOUT  (HO - KS + 1)     // 502
#define TW    32                // tile width (outputs)
#define TH    64                // tile height (outputs)
#define PW    (TW + KS - 1)     // 42
#define PH    (TH + KS - 1)     // 74
#define SW    43                // s12 row stride (ull) — odd, bank-friendly
#define HS    33                // hms/hx12 row stride (elements)
#define NTX   ((HOUT + TW - 1) / TW)   // 16
#define NTY   ((HOUT + TH - 1) / TH)   // 8

typedef unsigned long long ull;

// Gaussian weights (sigma=1.5, ks=11), double-normalized, rounded to f32.
#define GW0  0.0010283801f
#define GW1  0.0075987582f
#define GW2  0.0360007722f
#define GW3  0.1093606884f
#define GW4  0.2130055383f
#define GW5  0.2660117256f

__device__ double        g_accum = 0.0;
__device__ unsigned int  g_count = 0;

// ---------------- f32x2 packed helpers ----------------
__device__ __forceinline__ ull splat2(float g) {
    ull r; asm("mov.b64 %0, {%1, %1};" : "=l"(r) : "f"(g)); return r;
}
__device__ __forceinline__ void up2(ull v, float& lo, float& hi) {
    asm("mov.b64 {%0, %1}, %2;" : "=f"(lo), "=f"(hi) : "l"(v));
}
__device__ __forceinline__ ull pk2(float lo, float hi) {
    ull r; asm("mov.b64 %0, {%1, %2};" : "=l"(r) : "f"(lo), "f"(hi)); return r;
}
__device__ __forceinline__ ull pfma(ull a, ull b, ull c) {
    ull d; asm("fma.rn.f32x2 %0, %1, %2, %3;" : "=l"(d) : "l"(a), "l"(b), "l"(c)); return d;
}
__device__ __forceinline__ ull pmul(ull a, ull b) {
    ull d; asm("mul.rn.f32x2 %0, %1, %2;" : "=l"(d) : "l"(a), "l"(b)); return d;
}

#define GWC(k) ((k) < 6 ? (k) : 10 - (k))

// ---- dynamic smem layout (bytes) ----
#define OFF_S12   0                                  // ull  [PH][SW]  = 25456
#define OFF_HMS   (OFF_S12 + PH * SW * 8)            // ull2 [PH][HS]  = 39072
#define OFF_HX12  (OFF_HMS + PH * HS * 16)           // f32  [PH][HS]  =  9768
#define OFF_TBL   (OFF_HX12 + PH * HS * 4)           // tables
// row tables: iy0*HI, iy1*HI, wy, gy*HO  (PH each) ; col: ix0, ix1, wx, gx (PW each)
#define OFF_RED   (OFF_TBL + (PH * 4 + PW * 4) * 4)
#define SMEM_BYTES (OFF_RED + 64)                    // ~76.2KB total? compute: 25456+39072+9768+1856+64 = 76216

// ---------------- single fused kernel ----------------
__global__ void __launch_bounds__(256, 3)
ssim_tile_kernel(const float* __restrict__ input,   // [96, 384, 384]
                 const float* __restrict__ target,  // [96, 512, 512]
                 float* __restrict__ out,
                 long long count, unsigned int nblocks)
{
    extern __shared__ char smem[];
    ull        (*s12)[SW]  = (ull (*)[SW])(smem + OFF_S12);
    ulonglong2 (*hms)[HS]  = (ulonglong2 (*)[HS])(smem + OFF_HMS);
    float      (*hx12)[HS] = (float (*)[HS])(smem + OFF_HX12);
    int   *riy0 = (int*)  (smem + OFF_TBL);
    int   *riy1 = riy0 + PH;
    float *rwy  = (float*)(riy1 + PH);
    int   *rgy  = (int*)  (rwy + PH);
    int   *cix0 = rgy + PH;
    int   *cix1 = cix0 + PW;
    float *cwx  = (float*)(cix1 + PW);
    int   *cgx  = (int*)  (cwx + PW);
    float *redbuf = (float*)(smem + OFF_RED);

    const int img = blockIdx.z;
    const int ty0 = blockIdx.y * TH;
    const int tx0 = blockIdx.x * TW;
    const int tid = threadIdx.x;

    const float GW[6] = {GW0, GW1, GW2, GW3, GW4, GW5};
    ull CS[6];
    #pragma unroll
    for (int k = 0; k < 6; k++) CS[k] = splat2(GW[k]);

    const float* inp = input  + (size_t)img * (HI * HI);
    const float* tgt = target + (size_t)img * (HO * HO);

    // ---- build bilinear tables (row: tid<PH, col: tid in [128,128+PW)) ----
    if (tid < PH) {
        int gy = min(ty0 + tid, HO - 1);
        int py = gy * (HI - 1);
        int iy0 = py / (HO - 1);
        riy0[tid] = iy0 * HI;
        riy1[tid] = min(iy0 + 1, HI - 1) * HI;
        rwy[tid]  = (float)(py - iy0 * (HO - 1)) * (1.0f / (float)(HO - 1));
        rgy[tid]  = gy * HO;
    }
    if (tid >= 128 && tid < 128 + PW) {
        int c = tid - 128;
        int gx = min(tx0 + c, HO - 1);
        int px = gx * (HI - 1);
        int ix0 = px / (HO - 1);
        cix0[c] = ix0;
        cix1[c] = min(ix0 + 1, HI - 1);
        cwx[c]  = (float)(px - ix0 * (HO - 1)) * (1.0f / (float)(HO - 1));
        cgx[c]  = gx;
    }
    __syncthreads();

    // ---- load: target direct, img1 bilinear via tables ----
    for (int e = tid; e < PH * PW; e += 256) {
        int r = e / PW;
        int c = e - r * PW;

        float t2 = tgt[rgy[r] + cgx[c]];

        int   y0 = riy0[r], y1 = riy1[r];
        float wy = rwy[r];
        int   x0 = cix0[c], x1 = cix1[c];
        float wx = cwx[c];

        float a  = inp[y0 + x0];
        float b  = inp[y0 + x1];
        float cc = inp[y1 + x0];
        float d  = inp[y1 + x1];
        float top = a  + (b - a)  * wx;
        float bot = cc + (d - cc) * wx;
        float v1  = top + (bot - top) * wy;

        s12[r][c] = pk2(v1, t2);
    }
    __syncthreads();

    // ---- horizontal pass: 4 output cols per task, sliding 14-tap window ----
    for (int e = tid; e < PH * 8; e += 256) {
        int r  = e >> 3;
        int c0 = (e & 7) << 2;

        ull aM[4] = {0, 0, 0, 0};
        ull aS[4] = {0, 0, 0, 0};
        float aX[4] = {0.f, 0.f, 0.f, 0.f};

        #pragma unroll
        for (int j = 0; j < 14; j++) {
            ull pk = s12[r][c0 + j];
            float p1, p2;
            up2(pk, p1, p2);
            ull sq = pmul(pk, pk);
            float p12 = p1 * p2;
            #pragma unroll
            for (int o = 0; o < 4; o++) {
                int k = j - o;
                if (k >= 0 && k < KS) {
                    aM[o] = pfma(pk, CS[GWC(k)], aM[o]);
                    aS[o] = pfma(sq, CS[GWC(k)], aS[o]);
                    aX[o] = fmaf(GW[GWC(k)], p12, aX[o]);
                }
            }
        }
        #pragma unroll
        for (int o = 0; o < 4; o++) {
            hms[r][c0 + o]  = make_ulonglong2(aM[o], aS[o]);   // STS.128
            hx12[r][c0 + o] = aX[o];
        }
    }
    __syncthreads();

    // ---- vertical pass: 8 warps x 8 rows/thread, sliding 18-tap window ----
    const int lx = tid & 31;
    const int o0 = (tid >> 5) << 3;     // warp w -> rows 8w..8w+7

    ull aM[8], aS[8];
    float aX[8];
    #pragma unroll
    for (int o = 0; o < 8; o++) { aM[o] = 0; aS[o] = 0; aX[o] = 0.f; }

    #pragma unroll
    for (int rel = 0; rel < 18; rel++) {
        int rr = o0 + rel;
        ulonglong2 v = hms[rr][lx];     // LDS.128
        float vX = hx12[rr][lx];
        #pragma unroll
        for (int o = 0; o < 8; o++) {
            int k = rel - o;
            if (k >= 0 && k < KS) {
                aM[o] = pfma(v.x, CS[GWC(k)], aM[o]);
                aS[o] = pfma(v.y, CS[GWC(k)], aS[o]);
                aX[o] = fmaf(GW[GWC(k)], vX, aX[o]);
            }
        }
    }

    // ---- SSIM map + local sum ----
    const float C1 = 1e-4f;
    const float C2 = 9e-4f;
    float lsum = 0.f;
    const int gx = tx0 + lx;

    #pragma unroll
    for (int o = 0; o < 8; o++) {
        int gy = ty0 + o0 + o;
        if (gy < HOUT && gx < HOUT) {
            float mu1, mu2, x11, x22;
            up2(aM[o], mu1, mu2);
            up2(aS[o], x11, x22);
            float mu1sq = mu1 * mu1;
            float mu2sq = mu2 * mu2;
            float mu12  = mu1 * mu2;
            float sig1  = x11 - mu1sq;
            float sig2  = x22 - mu2sq;
            float sig12 = aX[o] - mu12;
            float v1 = 2.0f * sig12 + C2;
            float v2 = sig1 + sig2 + C2;
            float num = (2.0f * mu12 + C1) * v1;
            float den = (mu1sq + mu2sq + C1) * v2;
            lsum += __fdividef(num, den);
        }
    }

    // ---- block reduction (8 warps) ----
    #pragma unroll
    for (int off = 16; off > 0; off >>= 1)
        lsum += __shfl_down_sync(0xFFFFFFFFu, lsum, off);
    int lane = tid & 31;
    int wid  = tid >> 5;
    if (lane == 0) redbuf[wid] = lsum;
    __syncthreads();
    if (tid == 0) {
        float v = 0.f;
        #pragma unroll
        for (int w = 0; w < 8; w++) v += redbuf[w];
        atomicAdd(&g_accum, (double)v);
        __threadfence();
        unsigned int old = atomicAdd(&g_count, 1u);
        if (old == nblocks - 1u) {
            double mean = g_accum / (double)count;
            double loss = 1.0 - mean;
            if (loss < 0.0) loss = 0.0;
            if (loss > 1.0) loss = 1.0;
            out[0] = (float)loss;
            g_accum = 0.0;
            g_count = 0u;
        }
    }
}

extern "C" void kernel_launch(void* const* d_in, const int* in_sizes, int n_in,
                              void* d_out, int out_size) {
    const float* input  = (const float*)d_in[0];
    const float* target = (const float*)d_in[1];
    int sz0 = in_sizes[0], sz1 = in_sizes[1];
    if (sz0 > sz1) {
        const float* t = input; input = target; target = t;
        int ts = sz0; sz0 = sz1; sz1 = ts;
    }
    int n_img = sz0 / (HI * HI);   // 96

    static bool attr_set = false;
    if (!attr_set) {
        cudaFuncSetAttribute(ssim_tile_kernel,
                             cudaFuncAttributeMaxDynamicSharedMemorySize, SMEM_BYTES);
        attr_set = true;
    }

    dim3 grid(NTX, NTY, n_img);
    unsigned int nblocks = NTX * NTY * (unsigned int)n_img;
    long long count = (long long)n_img * HOUT * HOUT;

    ssim_tile_kernel<<<grid, 256, SMEM_BYTES>>>(input, target, (float*)d_out,
                                                count, nblocks);
}

// round 7
// speedup vs baseline: 1.1303x; 1.0631x over previous
#include <cuda_runtime.h>
#include <math.h>

// ---------------- problem constants ----------------
#define KS    11
#define HI    384
#define HO    512
#define HOUT  (HO - KS + 1)     // 502
#define TW    32                // tile width (outputs)
#define TH    64                // tile height (outputs)
#define PW    (TW + KS - 1)     // 42
#define PH    (TH + KS - 1)     // 74
#define SW    43                // s12 row stride (ull)
#define HS    33                // hbuf row stride (elements)
#define NTX   ((HOUT + TW - 1) / TW)   // 16
#define NTY   ((HOUT + TH - 1) / TH)   // 8

typedef unsigned long long ull;

// Gaussian weights (sigma=1.5, ks=11), double-normalized, rounded to f32.
#define GW0  0.0010283801f
#define GW1  0.0075987582f
#define GW2  0.0360007722f
#define GW3  0.1093606884f
#define GW4  0.2130055383f
#define GW5  0.2660117256f

__device__ double        g_accum = 0.0;
__device__ unsigned int  g_count = 0;

// ---------------- f32x2 packed helpers ----------------
__device__ __forceinline__ ull splat2(float g) {
    ull r; asm("mov.b64 %0, {%1, %1};" : "=l"(r) : "f"(g)); return r;
}
__device__ __forceinline__ void up2(ull v, float& lo, float& hi) {
    asm("mov.b64 {%0, %1}, %2;" : "=f"(lo), "=f"(hi) : "l"(v));
}
__device__ __forceinline__ ull pk2(float lo, float hi) {
    ull r; asm("mov.b64 %0, {%1, %2};" : "=l"(r) : "f"(lo), "f"(hi)); return r;
}
__device__ __forceinline__ ull pfma(ull a, ull b, ull c) {
    ull d; asm("fma.rn.f32x2 %0, %1, %2, %3;" : "=l"(d) : "l"(a), "l"(b), "l"(c)); return d;
}
__device__ __forceinline__ ull pmul(ull a, ull b) {
    ull d; asm("mul.rn.f32x2 %0, %1, %2;" : "=l"(d) : "l"(a), "l"(b)); return d;
}

#define GWC(k) ((k) < 6 ? (k) : 10 - (k))

// ---- dynamic smem layout (bytes) ----
#define OFF_S12   0                                  // ull  [PH][SW] = 25456
#define OFF_HMU   (OFF_S12 + PH * SW * 8)            // ull  [PH][HS] = 19536
#define OFF_HSQ   (OFF_HMU + PH * HS * 8)            // ull  [PH][HS] = 19536
#define OFF_HX12  (OFF_HSQ + PH * HS * 8)            // f32  [PH][HS] =  9768
#define OFF_TBL   (OFF_HX12 + PH * HS * 4)
#define OFF_RED   (OFF_TBL + (PH * 4 + PW * 4) * 4)  // tables = 1856
#define SMEM_BYTES (OFF_RED + 64)                    // 76216 B -> 2... (228-x) 3 CTAs need 228KB: 3*76216=228648 > 233472? 228KB=233472 OK

// ---------------- single fused kernel ----------------
__global__ void __launch_bounds__(256, 3)
ssim_tile_kernel(const float* __restrict__ input,   // [96, 384, 384]
                 const float* __restrict__ target,  // [96, 512, 512]
                 float* __restrict__ out,
                 long long count, unsigned int nblocks)
{
    extern __shared__ char smem[];
    ull   (*s12)[SW]  = (ull (*)[SW])(smem + OFF_S12);
    ull   (*hmu)[HS]  = (ull (*)[HS])(smem + OFF_HMU);
    ull   (*hsq)[HS]  = (ull (*)[HS])(smem + OFF_HSQ);
    float (*hx12)[HS] = (float (*)[HS])(smem + OFF_HX12);
    int   *riy0 = (int*)  (smem + OFF_TBL);
    int   *riy1 = riy0 + PH;
    float *rwy  = (float*)(riy1 + PH);
    int   *rgy  = (int*)  (rwy + PH);
    int   *cix0 = rgy + PH;
    int   *cix1 = cix0 + PW;
    float *cwx  = (float*)(cix1 + PW);
    int   *cgx  = (int*)  (cwx + PW);
    float *redbuf = (float*)(smem + OFF_RED);

    const int img = blockIdx.z;
    const int ty0 = blockIdx.y * TH;
    const int tx0 = blockIdx.x * TW;
    const int tid = threadIdx.x;

    const float GW[6] = {GW0, GW1, GW2, GW3, GW4, GW5};
    ull CS[6];
    #pragma unroll
    for (int k = 0; k < 6; k++) CS[k] = splat2(GW[k]);

    const float* inp = input  + (size_t)img * (HI * HI);
    const float* tgt = target + (size_t)img * (HO * HO);

    // ---- build bilinear tables ----
    if (tid < PH) {
        int gy = min(ty0 + tid, HO - 1);
        int py = gy * (HI - 1);
        int iy0 = py / (HO - 1);
        riy0[tid] = iy0 * HI;
        riy1[tid] = min(iy0 + 1, HI - 1) * HI;
        rwy[tid]  = (float)(py - iy0 * (HO - 1)) * (1.0f / (float)(HO - 1));
        rgy[tid]  = gy * HO;
    }
    if (tid >= 128 && tid < 128 + PW) {
        int c = tid - 128;
        int gx = min(tx0 + c, HO - 1);
        int px = gx * (HI - 1);
        int ix0 = px / (HO - 1);
        cix0[c] = ix0;
        cix1[c] = min(ix0 + 1, HI - 1);
        cwx[c]  = (float)(px - ix0 * (HO - 1)) * (1.0f / (float)(HO - 1));
        cgx[c]  = gx;
    }
    __syncthreads();

    // ---- load: target direct, img1 bilinear via tables ----
    for (int e = tid; e < PH * PW; e += 256) {
        int r = e / PW;
        int c = e - r * PW;

        float t2 = tgt[rgy[r] + cgx[c]];

        int   y0 = riy0[r], y1 = riy1[r];
        float wy = rwy[r];
        int   x0 = cix0[c], x1 = cix1[c];
        float wx = cwx[c];

        float a  = inp[y0 + x0];
        float b  = inp[y0 + x1];
        float cc = inp[y1 + x0];
        float d  = inp[y1 + x1];
        float top = a  + (b - a)  * wx;
        float bot = cc + (d - cc) * wx;
        float v1  = top + (bot - top) * wy;

        s12[r][c] = pk2(v1, t2);
    }
    __syncthreads();

    // ---- horizontal pass: 4 output cols per task, sliding 14-tap window ----
    for (int e = tid; e < PH * 8; e += 256) {
        int r  = e >> 3;
        int c0 = (e & 7) << 2;

        ull aM[4] = {0, 0, 0, 0};
        ull aS[4] = {0, 0, 0, 0};
        float aX[4] = {0.f, 0.f, 0.f, 0.f};

        #pragma unroll
        for (int j = 0; j < 14; j++) {
            ull pk = s12[r][c0 + j];
            float p1, p2;
            up2(pk, p1, p2);
            ull sq = pmul(pk, pk);
            float p12 = p1 * p2;
            #pragma unroll
            for (int o = 0; o < 4; o++) {
                int k = j - o;
                if (k >= 0 && k < KS) {
                    aM[o] = pfma(pk, CS[GWC(k)], aM[o]);
                    aS[o] = pfma(sq, CS[GWC(k)], aS[o]);
                    aX[o] = fmaf(GW[GWC(k)], p12, aX[o]);
                }
            }
        }
        #pragma unroll
        for (int o = 0; o < 4; o++) {
            hmu[r][c0 + o]  = aM[o];
            hsq[r][c0 + o]  = aS[o];
            hx12[r][c0 + o] = aX[o];
        }
    }
    __syncthreads();

    // ---- vertical pass: 8 warps x 8 rows/thread, sliding 18-tap window ----
    const int lx = tid & 31;
    const int o0 = (tid >> 5) << 3;     // warp w -> rows 8w..8w+7

    ull aM[8], aS[8];
    float aX[8];
    #pragma unroll
    for (int o = 0; o < 8; o++) { aM[o] = 0; aS[o] = 0; aX[o] = 0.f; }

    #pragma unroll
    for (int rel = 0; rel < 18; rel++) {
        int rr = o0 + rel;
        ull vM   = hmu[rr][lx];
        ull vS   = hsq[rr][lx];
        float vX = hx12[rr][lx];
        #pragma unroll
        for (int o = 0; o < 8; o++) {
            int k = rel - o;
            if (k >= 0 && k < KS) {
                aM[o] = pfma(vM, CS[GWC(k)], aM[o]);
                aS[o] = pfma(vS, CS[GWC(k)], aS[o]);
                aX[o] = fmaf(GW[GWC(k)], vX, aX[o]);
            }
        }
    }

    // ---- SSIM map + local sum ----
    const float C1 = 1e-4f;
    const float C2 = 9e-4f;
    float lsum = 0.f;
    const int gx = tx0 + lx;

    #pragma unroll
    for (int o = 0; o < 8; o++) {
        int gy = ty0 + o0 + o;
        if (gy < HOUT && gx < HOUT) {
            float mu1, mu2, x11, x22;
            up2(aM[o], mu1, mu2);
            up2(aS[o], x11, x22);
            float mu1sq = mu1 * mu1;
            float mu2sq = mu2 * mu2;
            float mu12  = mu1 * mu2;
            float sig1  = x11 - mu1sq;
            float sig2  = x22 - mu2sq;
            float sig12 = aX[o] - mu12;
            float v1 = 2.0f * sig12 + C2;
            float v2 = sig1 + sig2 + C2;
            float num = (2.0f * mu12 + C1) * v1;
            float den = (mu1sq + mu2sq + C1) * v2;
            lsum += __fdividef(num, den);
        }
    }

    // ---- block reduction (8 warps) ----
    #pragma unroll
    for (int off = 16; off > 0; off >>= 1)
        lsum += __shfl_down_sync(0xFFFFFFFFu, lsum, off);
    int lane = tid & 31;
    int wid  = tid >> 5;
    if (lane == 0) redbuf[wid] = lsum;
    __syncthreads();
    if (tid == 0) {
        float v = 0.f;
        #pragma unroll
        for (int w = 0; w < 8; w++) v += redbuf[w];
        atomicAdd(&g_accum, (double)v);
        __threadfence();
        unsigned int old = atomicAdd(&g_count, 1u);
        if (old == nblocks - 1u) {
            double mean = g_accum / (double)count;
            double loss = 1.0 - mean;
            if (loss < 0.0) loss = 0.0;
            if (loss > 1.0) loss = 1.0;
            out[0] = (float)loss;
            g_accum = 0.0;
            g_count = 0u;
        }
    }
}

extern "C" void kernel_launch(void* const* d_in, const int* in_sizes, int n_in,
                              void* d_out, int out_size) {
    const float* input  = (const float*)d_in[0];
    const float* target = (const float*)d_in[1];
    int sz0 = in_sizes[0], sz1 = in_sizes[1];
    if (sz0 > sz1) {
        const float* t = input; input = target; target = t;
        int ts = sz0; sz0 = sz1; sz1 = ts;
    }
    int n_img = sz0 / (HI * HI);   // 96

    static bool attr_set = false;
    if (!attr_set) {
        cudaFuncSetAttribute(ssim_tile_kernel,
                             cudaFuncAttributeMaxDynamicSharedMemorySize, SMEM_BYTES);
        attr_set = true;
    }

    dim3 grid(NTX, NTY, n_img);
    unsigned int nblocks = NTX * NTY * (unsigned int)n_img;
    long long count = (long long)n_img * HOUT * HOUT;

    ssim_tile_kernel<<<grid, 256, SMEM_BYTES>>>(input, target, (float*)d_out,
                                                count, nblocks);
}

// round 8
// speedup vs baseline: 1.1449x; 1.0129x over previous
#include <cuda_runtime.h>
#include <math.h>

// ---------------- problem constants ----------------
#define KS    11
#define HI    384
#define HO    512
#define HOUT  (HO - KS + 1)     // 502
#define TW    32                // tile width (outputs)
#define TH    64                // tile height (outputs)
#define PW    (TW + KS - 1)     // 42
#define PH    (TH + KS - 1)     // 74
#define SW    43                // s12 row stride (ull) — odd -> conflict-free row walks
#define HS    33                // hbuf row stride (elements)
#define NTX   ((HOUT + TW - 1) / TW)   // 16
#define NTY   ((HOUT + TH - 1) / TH)   // 8
#define HTASKS (PH * 8)         // 592 horizontal tasks

typedef unsigned long long ull;

// Gaussian weights (sigma=1.5, ks=11), double-normalized, rounded to f32.
#define GW0  0.0010283801f
#define GW1  0.0075987582f
#define GW2  0.0360007722f
#define GW3  0.1093606884f
#define GW4  0.2130055383f
#define GW5  0.2660117256f

__device__ double        g_accum = 0.0;
__device__ unsigned int  g_count = 0;

// ---------------- f32x2 packed helpers ----------------
__device__ __forceinline__ ull splat2(float g) {
    ull r; asm("mov.b64 %0, {%1, %1};" : "=l"(r) : "f"(g)); return r;
}
__device__ __forceinline__ void up2(ull v, float& lo, float& hi) {
    asm("mov.b64 {%0, %1}, %2;" : "=f"(lo), "=f"(hi) : "l"(v));
}
__device__ __forceinline__ ull pk2(float lo, float hi) {
    ull r; asm("mov.b64 %0, {%1, %2};" : "=l"(r) : "f"(lo), "f"(hi)); return r;
}
__device__ __forceinline__ ull pfma(ull a, ull b, ull c) {
    ull d; asm("fma.rn.f32x2 %0, %1, %2, %3;" : "=l"(d) : "l"(a), "l"(b), "l"(c)); return d;
}
__device__ __forceinline__ ull pmul(ull a, ull b) {
    ull d; asm("mul.rn.f32x2 %0, %1, %2;" : "=l"(d) : "l"(a), "l"(b)); return d;
}

#define GWC(k) ((k) < 6 ? (k) : 10 - (k))

// ---- dynamic smem layout (bytes) ----
#define OFF_S12   0                                  // ull  [PH][SW] = 25456
#define OFF_HMU   (OFF_S12 + PH * SW * 8)            // ull  [PH][HS] = 19536
#define OFF_HSQ   (OFF_HMU + PH * HS * 8)            // ull  [PH][HS] = 19536
#define OFF_HX12  (OFF_HSQ + PH * HS * 8)            // f32  [PH][HS] =  9768
#define OFF_TBL   (OFF_HX12 + PH * HS * 4)
#define OFF_RED   (OFF_TBL + (PH * 4 + PW * 4) * 4)  // tables = 1856
#define SMEM_BYTES (OFF_RED + 64)                    // 76216 B; 3 CTAs = 228.6KB <= 228KB carveout region OK

// ---------------- single fused kernel ----------------
__global__ void __launch_bounds__(256, 3)
ssim_tile_kernel(const float* __restrict__ input,   // [96, 384, 384]
                 const float* __restrict__ target,  // [96, 512, 512]
                 float* __restrict__ out,
                 long long count, unsigned int nblocks)
{
    extern __shared__ char smem[];
    ull   (*s12)[SW]  = (ull (*)[SW])(smem + OFF_S12);
    ull   (*hmu)[HS]  = (ull (*)[HS])(smem + OFF_HMU);
    ull   (*hsq)[HS]  = (ull (*)[HS])(smem + OFF_HSQ);
    float (*hx12)[HS] = (float (*)[HS])(smem + OFF_HX12);
    int   *riy0 = (int*)  (smem + OFF_TBL);
    int   *riy1 = riy0 + PH;
    float *rwy  = (float*)(riy1 + PH);
    int   *rgy  = (int*)  (rwy + PH);
    int   *cix0 = rgy + PH;
    int   *cix1 = cix0 + PW;
    float *cwx  = (float*)(cix1 + PW);
    int   *cgx  = (int*)  (cwx + PW);
    float *redbuf = (float*)(smem + OFF_RED);

    const int img = blockIdx.z;
    const int ty0 = blockIdx.y * TH;
    const int tx0 = blockIdx.x * TW;
    const int tid = threadIdx.x;

    const float GW[6] = {GW0, GW1, GW2, GW3, GW4, GW5};
    ull CS[6];
    #pragma unroll
    for (int k = 0; k < 6; k++) CS[k] = splat2(GW[k]);

    const float* inp = input  + (size_t)img * (HI * HI);
    const float* tgt = target + (size_t)img * (HO * HO);

    // ---- build bilinear tables ----
    if (tid < PH) {
        int gy = min(ty0 + tid, HO - 1);
        int py = gy * (HI - 1);
        int iy0 = py / (HO - 1);
        riy0[tid] = iy0 * HI;
        riy1[tid] = min(iy0 + 1, HI - 1) * HI;
        rwy[tid]  = (float)(py - iy0 * (HO - 1)) * (1.0f / (float)(HO - 1));
        rgy[tid]  = gy * HO;
    }
    if (tid >= 128 && tid < 128 + PW) {
        int c = tid - 128;
        int gx = min(tx0 + c, HO - 1);
        int px = gx * (HI - 1);
        int ix0 = px / (HO - 1);
        cix0[c] = ix0;
        cix1[c] = min(ix0 + 1, HI - 1);
        cwx[c]  = (float)(px - ix0 * (HO - 1)) * (1.0f / (float)(HO - 1));
        cgx[c]  = gx;
    }
    __syncthreads();

    // ---- load: target direct, img1 bilinear via tables ----
    for (int e = tid; e < PH * PW; e += 256) {
        int r = e / PW;
        int c = e - r * PW;

        float t2 = tgt[rgy[r] + cgx[c]];

        int   y0 = riy0[r], y1 = riy1[r];
        float wy = rwy[r];
        int   x0 = cix0[c], x1 = cix1[c];
        float wx = cwx[c];

        float a  = inp[y0 + x0];
        float b  = inp[y0 + x1];
        float cc = inp[y1 + x0];
        float d  = inp[y1 + x1];
        float top = a  + (b - a)  * wx;
        float bot = cc + (d - cc) * wx;
        float v1  = top + (bot - top) * wy;

        s12[r][c] = pk2(v1, t2);
    }
    __syncthreads();

    // ---- horizontal pass: 4 output cols per task, sliding 14-tap window.
    //      Task map: r = e % PH, c0 = (e / PH) * 4  -> consecutive lanes walk
    //      consecutive rows; row stride 43 ull (odd) => conflict-free LDS.64. ----
    for (int e = tid; e < HTASKS; e += 256) {
        int g  = e / PH;            // column group 0..7
        int r  = e - g * PH;        // row 0..73
        int c0 = g << 2;

        ull aM[4] = {0, 0, 0, 0};
        ull aS[4] = {0, 0, 0, 0};
        float aX[4] = {0.f, 0.f, 0.f, 0.f};

        #pragma unroll
        for (int j = 0; j < 14; j++) {
            ull pk = s12[r][c0 + j];
            float p1, p2;
            up2(pk, p1, p2);
            ull sq = pmul(pk, pk);
            float p12 = p1 * p2;
            #pragma unroll
            for (int o = 0; o < 4; o++) {
                int k = j - o;
                if (k >= 0 && k < KS) {
                    aM[o] = pfma(pk, CS[GWC(k)], aM[o]);
                    aS[o] = pfma(sq, CS[GWC(k)], aS[o]);
                    aX[o] = fmaf(GW[GWC(k)], p12, aX[o]);
                }
            }
        }
        #pragma unroll
        for (int o = 0; o < 4; o++) {
            hmu[r][c0 + o]  = aM[o];
            hsq[r][c0 + o]  = aS[o];
            hx12[r][c0 + o] = aX[o];
        }
    }
    __syncthreads();

    // ---- vertical pass: 8 warps x 8 rows/thread, sliding 18-tap window ----
    const int lx = tid & 31;
    const int o0 = (tid >> 5) << 3;     // warp w -> rows 8w..8w+7

    ull aM[8], aS[8];
    float aX[8];
    #pragma unroll
    for (int o = 0; o < 8; o++) { aM[o] = 0; aS[o] = 0; aX[o] = 0.f; }

    #pragma unroll
    for (int rel = 0; rel < 18; rel++) {
        int rr = o0 + rel;
        ull vM   = hmu[rr][lx];
        ull vS   = hsq[rr][lx];
        float vX = hx12[rr][lx];
        #pragma unroll
        for (int o = 0; o < 8; o++) {
            int k = rel - o;
            if (k >= 0 && k < KS) {
                aM[o] = pfma(vM, CS[GWC(k)], aM[o]);
                aS[o] = pfma(vS, CS[GWC(k)], aS[o]);
                aX[o] = fmaf(GW[GWC(k)], vX, aX[o]);
            }
        }
    }

    // ---- SSIM map + local sum ----
    const float C1 = 1e-4f;
    const float C2 = 9e-4f;
    float lsum = 0.f;
    const int gx = tx0 + lx;

    #pragma unroll
    for (int o = 0; o < 8; o++) {
        int gy = ty0 + o0 + o;
        if (gy < HOUT && gx < HOUT) {
            float mu1, mu2, x11, x22;
            up2(aM[o], mu1, mu2);
            up2(aS[o], x11, x22);
            float mu1sq = mu1 * mu1;
            float mu2sq = mu2 * mu2;
            float mu12  = mu1 * mu2;
            float sig1  = x11 - mu1sq;
            float sig2  = x22 - mu2sq;
            float sig12 = aX[o] - mu12;
            float v1 = 2.0f * sig12 + C2;
            float v2 = sig1 + sig2 + C2;
            float num = (2.0f * mu12 + C1) * v1;
            float den = (mu1sq + mu2sq + C1) * v2;
            lsum += __fdividef(num, den);
        }
    }

    // ---- block reduction (8 warps) ----
    #pragma unroll
    for (int off = 16; off > 0; off >>= 1)
        lsum += __shfl_down_sync(0xFFFFFFFFu, lsum, off);
    int lane = tid & 31;
    int wid  = tid >> 5;
    if (lane == 0) redbuf[wid] = lsum;
    __syncthreads();
    if (tid == 0) {
        float v = 0.f;
        #pragma unroll
        for (int w = 0; w < 8; w++) v += redbuf[w];
        atomicAdd(&g_accum, (double)v);
        __threadfence();
        unsigned int old = atomicAdd(&g_count, 1u);
        if (old == nblocks - 1u) {
            double mean = g_accum / (double)count;
            double loss = 1.0 - mean;
            if (loss < 0.0) loss = 0.0;
            if (loss > 1.0) loss = 1.0;
            out[0] = (float)loss;
            g_accum = 0.0;
            g_count = 0u;
        }
    }
}

extern "C" void kernel_launch(void* const* d_in, const int* in_sizes, int n_in,
                              void* d_out, int out_size) {
    const float* input  = (const float*)d_in[0];
    const float* target = (const float*)d_in[1];
    int sz0 = in_sizes[0], sz1 = in_sizes[1];
    if (sz0 > sz1) {
        const float* t = input; input = target; target = t;
        int ts = sz0; sz0 = sz1; sz1 = ts;
    }
    int n_img = sz0 / (HI * HI);   // 96

    static bool attr_set = false;
    if (!attr_set) {
        cudaFuncSetAttribute(ssim_tile_kernel,
                             cudaFuncAttributeMaxDynamicSharedMemorySize, SMEM_BYTES);
        attr_set = true;
    }

    dim3 grid(NTX, NTY, n_img);
    unsigned int nblocks = NTX * NTY * (unsigned int)n_img;
    long long count = (long long)n_img * HOUT * HOUT;

    ssim_tile_kernel<<<grid, 256, SMEM_BYTES>>>(input, target, (float*)d_out,
                                                count, nblocks);
}